// round 6
// baseline (speedup 1.0000x reference)
#include <cuda_runtime.h>
#include <cuda_fp16.h>
#include <math.h>

#define Nn 100000
#define Ee 1600000
#define Hh 64
#define Ll 3
#define Kt 8192
#define CUT 5.0f
#define INVBN 0.9995003747f   // 1/sqrt(1+1e-3)
#define NB1 196               // ceil(Nn/512) scan blocks

typedef unsigned long long ull;

// ---- static device scratch ----
__device__ __align__(256) float  g_h[Nn * Hh];      // node features fp32, 25.6 MB
__device__ __align__(256) __half g_hh[Nn * Hh];     // fp16 gather mirror, 12.8 MB
__device__ __align__(256) float  g_agg[Nn * Hh];    // aggregation target, 25.6 MB
__device__ __align__(256) int4   g_ep4[Ee];         // (col, fs0, fs1, fs2), 25.6 MB
__device__ int   g_cnt[Nn];
__device__ int   g_off[Nn];
__device__ int   g_cur[Nn];
__device__ int   g_bsum[NB1];
__device__ int   g_bpre[NB1];
__device__ float g_table[Ll * Kt];
__device__ float g_w2s[Ll * Hh];
__device__ float g_b2s[Ll];
__device__ float g_mean[Hh];

__device__ __forceinline__ float sp(float x) {      // softplus, stable
    return fmaxf(x, 0.0f) + log1pf(expf(-fabsf(x)));
}

// ---- f32x2 helpers ----
__device__ __forceinline__ ull pk2(float a, float b) {
    ull r; asm("mov.b64 %0,{%1,%2};" : "=l"(r) : "f"(a), "f"(b)); return r;
}
__device__ __forceinline__ float2 up2(ull v) {
    float2 f; asm("mov.b64 {%0,%1},%2;" : "=f"(f.x), "=f"(f.y) : "l"(v)); return f;
}
__device__ __forceinline__ ull fma2(ull a, ull b, ull c) {
    ull d; asm("fma.rn.f32x2 %0,%1,%2,%3;" : "=l"(d) : "l"(a), "l"(b), "l"(c)); return d;
}

// ---- prep: fW2 rowsums, fb2 sums, zero mean accumulator ----
__global__ void prep_kernel(const float* __restrict__ fW2,
                            const float* __restrict__ fb2) {
    int t = threadIdx.x;
    if (t < Ll * Hh) {
        int l = t >> 6, j = t & 63;
        const float* p = fW2 + l * Hh * Hh + j * Hh;
        float s = 0.0f;
        #pragma unroll
        for (int k = 0; k < Hh; k++) s += p[k];
        g_w2s[t] = s;
    }
    if (t < Ll) {
        float s = 0.0f;
        for (int k = 0; k < Hh; k++) s += fb2[t * Hh + k];
        g_b2s[t] = s;
    }
    if (t < Hh) g_mean[t] = 0.0f;
}

// ---- table: fs(d) * cutoff(d) ----
__global__ void table_kernel(const float* __restrict__ fW1,
                             const float* __restrict__ fb1) {
    int t = blockIdx.x * blockDim.x + threadIdx.x;
    if (t >= Ll * Kt) return;
    int l = t >> 13;
    int k = t & (Kt - 1);
    float d = k * (CUT / (float)(Kt - 1));
    float s = d * (2.0f / CUT) - 1.0f;
    const float* w1 = fW1 + l * Hh;
    const float* b1 = fb1 + l * Hh;
    const float* w2 = g_w2s + l * Hh;
    float acc = g_b2s[l];
    #pragma unroll 8
    for (int j = 0; j < Hh; j++)
        acc = fmaf(tanhf(fmaf(s, w1[j], b1[j])), w2[j], acc);
    float cut = 0.5f * (cosf(d * (float)(M_PI / 5.0)) + 1.0f);
    g_table[t] = acc * cut;
}

// ---- embedding: h = x @ emb_W + emb_b ; also fp16 mirror ----
__global__ void embed_kernel(const float* __restrict__ x,
                             const float* __restrict__ W,
                             const float* __restrict__ b) {
    __shared__ float sW[16 * 64];
    __shared__ float sb[64];
    int tid = threadIdx.x;
    for (int i = tid; i < 16 * 64; i += 256) sW[i] = W[i];
    if (tid < 64) sb[tid] = b[tid];
    __syncthreads();
    int t = blockIdx.x * 256 + tid;
    if (t >= Nn * 16) return;
    int n = t >> 4, q = t & 15, j0 = q * 4;
    const float* xr = x + n * 16;
    float4 acc = make_float4(sb[j0], sb[j0 + 1], sb[j0 + 2], sb[j0 + 3]);
    #pragma unroll
    for (int i = 0; i < 16; i++) {
        float xi = xr[i];
        acc.x = fmaf(xi, sW[i * 64 + j0 + 0], acc.x);
        acc.y = fmaf(xi, sW[i * 64 + j0 + 1], acc.y);
        acc.z = fmaf(xi, sW[i * 64 + j0 + 2], acc.z);
        acc.w = fmaf(xi, sW[i * 64 + j0 + 3], acc.w);
    }
    ((float4*)g_h)[t] = acc;
    __half2* hh = (__half2*)(g_hh + n * 64 + j0);
    hh[0] = __floats2half2_rn(acc.x, acc.y);
    hh[1] = __floats2half2_rn(acc.z, acc.w);
}

// ============ CSR build ============
__global__ void zcnt_kernel() {
    int i = blockIdx.x * blockDim.x + threadIdx.x;
    if (i < Nn) g_cnt[i] = 0;
}

__global__ void hist_kernel(const int* __restrict__ eidx) {
    int e = blockIdx.x * blockDim.x + threadIdx.x;
    if (e < Ee) atomicAdd(&g_cnt[eidx[e]], 1);
}

__global__ void scan1_kernel() {
    int i = blockIdx.x * 512 + threadIdx.x;
    int v = (i < Nn) ? g_cnt[i] : 0;
    int lane = threadIdx.x & 31, w = threadIdx.x >> 5;
    int x = v;
    #pragma unroll
    for (int off = 1; off < 32; off <<= 1) {
        int y = __shfl_up_sync(0xffffffff, x, off);
        if (lane >= off) x += y;
    }
    __shared__ int wsum[16], wpre[16];
    if (lane == 31) wsum[w] = x;
    __syncthreads();
    if (threadIdx.x < 16) {
        int s = wsum[threadIdx.x];
        int xs = s;
        #pragma unroll
        for (int off = 1; off < 16; off <<= 1) {
            int y = __shfl_up_sync(0x0000ffff, xs, off);
            if ((int)threadIdx.x >= off) xs += y;
        }
        wpre[threadIdx.x] = xs - s;
        if (threadIdx.x == 15) g_bsum[blockIdx.x] = xs;
    }
    __syncthreads();
    if (i < Nn) g_off[i] = x - v + wpre[w];
}

__global__ void scan2_kernel() {
    int t = threadIdx.x;
    int v = (t < NB1) ? g_bsum[t] : 0;
    int lane = t & 31, w = t >> 5;
    int x = v;
    #pragma unroll
    for (int off = 1; off < 32; off <<= 1) {
        int y = __shfl_up_sync(0xffffffff, x, off);
        if (lane >= off) x += y;
    }
    __shared__ int wsum[8], wpre[8];
    if (lane == 31) wsum[w] = x;
    __syncthreads();
    if (t < 8) {
        int s = wsum[t];
        int xs = s;
        #pragma unroll
        for (int off = 1; off < 8; off <<= 1) {
            int y = __shfl_up_sync(0x000000ff, xs, off);
            if (t >= off) xs += y;
        }
        wpre[t] = xs - s;
    }
    __syncthreads();
    if (t < NB1) g_bpre[t] = x - v + wpre[w];
}

__global__ void scan3_kernel() {
    int i = blockIdx.x * 512 + threadIdx.x;
    if (i < Nn) {
        int o = g_off[i] + g_bpre[blockIdx.x];
        g_off[i] = o;
        g_cur[i] = o;
    }
}

// scatter edges into CSR order; one int4 record (col, fs0, fs1, fs2)
__global__ void fill_kernel(const int* __restrict__ eidx,
                            const float* __restrict__ dist) {
    int e = blockIdx.x * blockDim.x + threadIdx.x;
    if (e >= Ee) return;
    int r = eidx[e];
    int c = eidx[Ee + e];
    float d = __ldg(dist + e);
    float u = d * ((float)(Kt - 1) / CUT);
    u = fminf(fmaxf(u, 0.0f), (float)(Kt - 2) + 0.999f);
    int i = (int)u;
    float fr = u - (float)i;
    float fs[Ll];
    #pragma unroll
    for (int l = 0; l < Ll; l++) {
        const float* tb = g_table + l * Kt;
        float t0 = __ldg(tb + i), t1 = __ldg(tb + i + 1);
        fs[l] = fmaf(fr, t1 - t0, t0);
    }
    int pos = atomicAdd(&g_cur[r], 1);
    g_ep4[pos] = make_int4(c, __float_as_int(fs[0]),
                           __float_as_int(fs[1]), __float_as_int(fs[2]));
}

// ============ per-layer edge aggregation: warp per row, fp16 gather, 4-way ILP
__global__ void __launch_bounds__(256) agg_kernel(int l) {
    int gw = (blockIdx.x * 256 + threadIdx.x) >> 5;
    if (gw >= Nn) return;
    int lane = threadIdx.x & 31, sub = lane & 7, par = lane >> 3;
    int beg = g_off[gw], end = beg + g_cnt[gw];
    float acc[8];
    #pragma unroll
    for (int k = 0; k < 8; k++) acc[k] = 0.0f;
    #pragma unroll 2
    for (int e = beg + par; e < end; e += 4) {
        int4 m = __ldg(&g_ep4[e]);
        float fs = __int_as_float(l == 0 ? m.y : (l == 1 ? m.z : m.w));
        float4 raw = __ldg((const float4*)(g_hh + m.x * 64) + sub);
        float2 f0 = __half22float2(*(__half2*)&raw.x);
        float2 f1 = __half22float2(*((__half2*)&raw.x + 1));
        float2 f2 = __half22float2(*(__half2*)&raw.z);
        float2 f3 = __half22float2(*((__half2*)&raw.z + 1));
        acc[0] = fmaf(f0.x, fs, acc[0]);
        acc[1] = fmaf(f0.y, fs, acc[1]);
        acc[2] = fmaf(f1.x, fs, acc[2]);
        acc[3] = fmaf(f1.y, fs, acc[3]);
        acc[4] = fmaf(f2.x, fs, acc[4]);
        acc[5] = fmaf(f2.y, fs, acc[5]);
        acc[6] = fmaf(f3.x, fs, acc[6]);
        acc[7] = fmaf(f3.y, fs, acc[7]);
    }
    #pragma unroll
    for (int k = 0; k < 8; k++) {
        acc[k] += __shfl_xor_sync(0xffffffff, acc[k], 8);
        acc[k] += __shfl_xor_sync(0xffffffff, acc[k], 16);
    }
    if (par == 0) {
        float4* dst = (float4*)(g_agg + gw * 64);
        dst[sub * 2 + 0] = make_float4(acc[0], acc[1], acc[2], acc[3]);
        dst[sub * 2 + 1] = make_float4(acc[4], acc[5], acc[6], acc[7]);
    }
}

// ============ node MLP: packed f32x2 weights, thread-per-column ============
__global__ void __launch_bounds__(128, 3) node_kernel(
    const float* __restrict__ iW1, const float* __restrict__ ib1,
    const float* __restrict__ iW2, const float* __restrict__ ib2,
    const float* __restrict__ gam, const float* __restrict__ bet,
    int flags) {   // bit0: accumulate mean; bit1: write fp16 mirror
    __shared__ __align__(16) float sa[2][64];
    __shared__ __align__(16) float st[2][64];
    __shared__ float sm[128];
    int tid = threadIdx.x;
    int half_ = tid >> 6, j = tid & 63;
    ull w1[32], w2[32];
    #pragma unroll
    for (int i = 0; i < 32; i++) {
        w1[i] = pk2(iW1[(2 * i) * 64 + j], iW1[(2 * i + 1) * 64 + j]);
        w2[i] = pk2(iW2[(2 * i) * 64 + j], iW2[(2 * i + 1) * 64 + j]);
    }
    float b1 = ib1[j], b2 = ib2[j];
    float gm = gam[j] * INVBN, bt = bet[j];
    float ms = 0.0f;
    int do_mean = flags & 1, do_half = flags & 2;

    for (int n0 = blockIdx.x * 2; n0 < Nn; n0 += gridDim.x * 2) {
        int n = n0 + half_;             // Nn even -> always valid
        sa[half_][j] = g_agg[n * 64 + j];
        __syncthreads();
        ull acc = 0ull;
        const ulonglong2* A = (const ulonglong2*)sa[half_];
        #pragma unroll
        for (int i4 = 0; i4 < 16; i4++) {
            ulonglong2 av = A[i4];
            acc = fma2(av.x, w1[2 * i4 + 0], acc);
            acc = fma2(av.y, w1[2 * i4 + 1], acc);
        }
        float2 f1 = up2(acc);
        float t = sp(f1.x + f1.y + b1);
        st[half_][j] = t;
        __syncthreads();
        ull acc2 = 0ull;
        const ulonglong2* T = (const ulonglong2*)st[half_];
        #pragma unroll
        for (int i4 = 0; i4 < 16; i4++) {
            ulonglong2 tv = T[i4];
            acc2 = fma2(tv.x, w2[2 * i4 + 0], acc2);
            acc2 = fma2(tv.y, w2[2 * i4 + 1], acc2);
        }
        float2 f2 = up2(acc2);
        float o = f2.x + f2.y + b2;
        float hn = g_h[n * 64 + j] + fmaf(o, gm, bt);
        g_h[n * 64 + j] = hn;
        if (do_half) g_hh[n * 64 + j] = __float2half_rn(hn);
        ms += hn;
    }
    if (do_mean) {
        sm[tid] = ms;
        __syncthreads();
        if (half_ == 0) atomicAdd(&g_mean[j], sm[j] + sm[j + 64]);
    }
}

// ---- final head ----
__global__ void final_kernel(const float* __restrict__ oW1, const float* __restrict__ ob1,
                             const float* __restrict__ og1, const float* __restrict__ obt1,
                             const float* __restrict__ oW2, const float* __restrict__ ob2,
                             const float* __restrict__ og2, const float* __restrict__ obt2,
                             const float* __restrict__ fiW, const float* __restrict__ fib,
                             float* __restrict__ out) {
    __shared__ float gv[64], s1[32], s2[32];
    int t = threadIdx.x;  // 64 threads
    gv[t] = g_mean[t] * (1.0f / (float)Nn);
    __syncthreads();
    if (t < 32) {
        float acc = ob1[t];
        #pragma unroll
        for (int i = 0; i < 64; i++) acc = fmaf(gv[i], oW1[i * 32 + t], acc);
        s1[t] = fmaf(sp(acc) * INVBN, og1[t], obt1[t]);
    }
    __syncthreads();
    if (t < 32) {
        float acc = ob2[t];
        #pragma unroll
        for (int i = 0; i < 32; i++) acc = fmaf(s1[i], oW2[i * 32 + t], acc);
        s2[t] = fmaf(sp(acc) * INVBN, og2[t], obt2[t]);
    }
    __syncthreads();
    if (t < 3) {
        float acc = fib[t];
        #pragma unroll
        for (int i = 0; i < 32; i++) acc = fmaf(s2[i], fiW[i * 3 + t], acc);
        out[t] = acc;
    }
}

extern "C" void kernel_launch(void* const* d_in, const int* in_sizes, int n_in,
                              void* d_out, int out_size) {
    const float* x    = (const float*)d_in[0];
    const int*   eidx = (const int*)  d_in[1];
    const float* dist = (const float*)d_in[2];
    const float* embW = (const float*)d_in[4];
    const float* embB = (const float*)d_in[5];
    const float* fW1  = (const float*)d_in[6];
    const float* fb1  = (const float*)d_in[7];
    const float* fW2  = (const float*)d_in[8];
    const float* fb2  = (const float*)d_in[9];
    const float* iW1  = (const float*)d_in[10];
    const float* ib1  = (const float*)d_in[11];
    const float* iW2  = (const float*)d_in[12];
    const float* ib2  = (const float*)d_in[13];
    const float* gam  = (const float*)d_in[14];
    const float* bet  = (const float*)d_in[15];
    const float* oW1  = (const float*)d_in[16];
    const float* ob1  = (const float*)d_in[17];
    const float* og1  = (const float*)d_in[18];
    const float* obt1 = (const float*)d_in[19];
    const float* oW2  = (const float*)d_in[20];
    const float* ob2  = (const float*)d_in[21];
    const float* og2  = (const float*)d_in[22];
    const float* obt2 = (const float*)d_in[23];
    const float* fiW  = (const float*)d_in[24];
    const float* fib  = (const float*)d_in[25];
    float* out = (float*)d_out;

    prep_kernel<<<1, 256>>>(fW2, fb2);
    table_kernel<<<(Ll * Kt + 255) / 256, 256>>>(fW1, fb1);
    embed_kernel<<<(Nn * 16 + 255) / 256, 256>>>(x, embW, embB);

    zcnt_kernel<<<(Nn + 1023) / 1024, 1024>>>();
    hist_kernel<<<(Ee + 255) / 256, 256>>>(eidx);
    scan1_kernel<<<NB1, 512>>>();
    scan2_kernel<<<1, 256>>>();
    scan3_kernel<<<NB1, 512>>>();
    fill_kernel<<<(Ee + 255) / 256, 256>>>(eidx, dist);

    for (int l = 0; l < Ll; l++) {
        agg_kernel<<<(Nn * 32 + 255) / 256, 256>>>(l);
        int flags = (l == Ll - 1) ? 1 : 2;   // last: mean, no mirror; else mirror
        node_kernel<<<444, 128>>>(iW1 + l * 4096, ib1 + l * 64,
                                  iW2 + l * 4096, ib2 + l * 64,
                                  gam + l * 64, bet + l * 64, flags);
    }

    final_kernel<<<1, 64>>>(oW1, ob1, og1, obt1, oW2, ob2, og2, obt2,
                            fiW, fib, out);
}

// round 7
// speedup vs baseline: 1.1938x; 1.1938x over previous
#include <cuda_runtime.h>
#include <math.h>

#define Nn 100000
#define Ee 1600000
#define Hh 64
#define Ll 3
#define Kt 8192
#define CUT 5.0f
#define INVBN 0.9995003747f   // 1/sqrt(1+1e-3)
#define NB1 196               // ceil(Nn/512) scan blocks

typedef unsigned long long ull;

// ---- static device scratch ----
__device__ __align__(256) float g_h[Nn * Hh];       // node features, 25.6 MB
__device__ __align__(256) float g_agg[Nn * Hh];     // aggregation target, 25.6 MB
__device__ __align__(256) int4  g_ep4[Ee];          // (col, fs0, fs1, fs2), 25.6 MB
__device__ int   g_cnt[Nn];
__device__ int   g_off[Nn];
__device__ int   g_cur[Nn];
__device__ ull   g_state[NB1];                      // lookback scan states
__device__ float g_table[Ll * Kt];
__device__ float g_mean[Hh];

__device__ __forceinline__ float sp(float x) {      // softplus, stable
    return fmaxf(x, 0.0f) + log1pf(expf(-fabsf(x)));
}

// ---- table: fs(d)*cut(d); fW2 rowsums computed per-block in smem ----
__global__ void table_kernel(const float* __restrict__ fW1,
                             const float* __restrict__ fb1,
                             const float* __restrict__ fW2,
                             const float* __restrict__ fb2) {
    int t = blockIdx.x * 256 + threadIdx.x;       // grid 96x256 == Ll*Kt
    int l = t >> 13;                              // same l for whole block
    __shared__ float sw2[64];
    __shared__ float sb2;
    if (threadIdx.x < 64) {
        const float* p = fW2 + l * Hh * Hh + threadIdx.x * Hh;
        float s = 0.0f;
        #pragma unroll
        for (int k = 0; k < Hh; k++) s += p[k];
        sw2[threadIdx.x] = s;
    }
    if (threadIdx.x == 64) {
        float s = 0.0f;
        for (int k = 0; k < Hh; k++) s += fb2[l * Hh + k];
        sb2 = s;
    }
    __syncthreads();
    int k = t & (Kt - 1);
    float d = k * (CUT / (float)(Kt - 1));
    float s = d * (2.0f / CUT) - 1.0f;
    const float* w1 = fW1 + l * Hh;
    const float* b1 = fb1 + l * Hh;
    float acc = sb2;
    #pragma unroll 8
    for (int j = 0; j < Hh; j++)
        acc = fmaf(tanhf(fmaf(s, w1[j], b1[j])), sw2[j], acc);
    float cut = 0.5f * (cosf(d * (float)(M_PI / 5.0)) + 1.0f);
    g_table[t] = acc * cut;
}

// ---- embedding: h = x @ emb_W + emb_b ; also zero cnt/mean/scan-state ----
__global__ void embed_kernel(const float* __restrict__ x,
                             const float* __restrict__ W,
                             const float* __restrict__ b) {
    __shared__ float sW[16 * 64];
    __shared__ float sb[64];
    int tid = threadIdx.x;
    for (int i = tid; i < 16 * 64; i += 256) sW[i] = W[i];
    if (tid < 64) sb[tid] = b[tid];
    __syncthreads();
    int t = blockIdx.x * 256 + tid;
    // side duties (disjoint ranges, cheap)
    if (t < Nn) g_cnt[t] = 0;
    if (t < Hh) g_mean[t] = 0.0f;
    if (t < NB1) g_state[t] = 0ull;
    if (t >= Nn * 16) return;
    int n = t >> 4, q = t & 15, j0 = q * 4;
    const float* xr = x + n * 16;
    float4 acc = make_float4(sb[j0], sb[j0 + 1], sb[j0 + 2], sb[j0 + 3]);
    #pragma unroll
    for (int i = 0; i < 16; i++) {
        float xi = xr[i];
        acc.x = fmaf(xi, sW[i * 64 + j0 + 0], acc.x);
        acc.y = fmaf(xi, sW[i * 64 + j0 + 1], acc.y);
        acc.z = fmaf(xi, sW[i * 64 + j0 + 2], acc.z);
        acc.w = fmaf(xi, sW[i * 64 + j0 + 3], acc.w);
    }
    ((float4*)g_h)[t] = acc;
}

__global__ void hist_kernel(const int* __restrict__ eidx) {
    int e = blockIdx.x * blockDim.x + threadIdx.x;
    if (e < Ee) atomicAdd(&g_cnt[eidx[e]], 1);
}

// ---- single-pass decoupled-lookback exclusive scan of g_cnt -> g_off/g_cur ----
__global__ void scan_kernel() {
    int bid = blockIdx.x;
    int i = bid * 512 + threadIdx.x;
    int v = (i < Nn) ? g_cnt[i] : 0;
    int lane = threadIdx.x & 31, w = threadIdx.x >> 5;
    int x = v;
    #pragma unroll
    for (int off = 1; off < 32; off <<= 1) {
        int y = __shfl_up_sync(0xffffffff, x, off);
        if (lane >= off) x += y;
    }
    __shared__ int wsum[16], wpre[16];
    __shared__ int stotal, sprefix;
    if (lane == 31) wsum[w] = x;
    __syncthreads();
    if (threadIdx.x < 16) {
        int s = wsum[threadIdx.x];
        int xs = s;
        #pragma unroll
        for (int off = 1; off < 16; off <<= 1) {
            int y = __shfl_up_sync(0x0000ffff, xs, off);
            if ((int)threadIdx.x >= off) xs += y;
        }
        wpre[threadIdx.x] = xs - s;
        if (threadIdx.x == 15) stotal = xs;
    }
    __syncthreads();
    int total = stotal;
    if (threadIdx.x == 0) {
        if (bid == 0) {
            sprefix = 0;
            atomicExch(&g_state[0], (2ull << 32) | (unsigned)total);
        } else {
            atomicExch(&g_state[bid], (1ull << 32) | (unsigned)total);
            ull run = 0;
            int p = bid - 1;
            while (true) {
                ull sv = atomicAdd(&g_state[p], 0ull);
                unsigned st = (unsigned)(sv >> 32);
                if (st == 0u) { __nanosleep(32); continue; }
                run += (unsigned)sv;
                if (st == 2u) break;
                p--;
            }
            sprefix = (int)run;
            atomicExch(&g_state[bid], (2ull << 32) | (unsigned)(run + total));
        }
    }
    __syncthreads();
    if (i < Nn) {
        int o = x - v + wpre[w] + sprefix;
        g_off[i] = o;
        g_cur[i] = o;
    }
}

// scatter edges into CSR order; one int4 record (col, fs0, fs1, fs2)
__global__ void fill_kernel(const int* __restrict__ eidx,
                            const float* __restrict__ dist) {
    int e = blockIdx.x * blockDim.x + threadIdx.x;
    if (e >= Ee) return;
    int r = eidx[e];
    int c = eidx[Ee + e];
    float d = __ldg(dist + e);
    float u = d * ((float)(Kt - 1) / CUT);
    u = fminf(fmaxf(u, 0.0f), (float)(Kt - 2) + 0.999f);
    int i = (int)u;
    float fr = u - (float)i;
    float fs[Ll];
    #pragma unroll
    for (int l = 0; l < Ll; l++) {
        const float* tb = g_table + l * Kt;
        float t0 = __ldg(tb + i), t1 = __ldg(tb + i + 1);
        fs[l] = fmaf(fr, t1 - t0, t0);
    }
    int pos = atomicAdd(&g_cur[r], 1);
    g_ep4[pos] = make_int4(c, __float_as_int(fs[0]),
                           __float_as_int(fs[1]), __float_as_int(fs[2]));
}

// ============ per-layer edge aggregation: warp per row, 2-deep unroll ============
__global__ void __launch_bounds__(256) agg_kernel(int l) {
    int gw = (blockIdx.x * 256 + threadIdx.x) >> 5;
    if (gw >= Nn) return;
    int lane = threadIdx.x & 31, sub = lane & 15, par = lane >> 4;
    int beg = g_off[gw], end = beg + g_cnt[gw];
    float4 acc = make_float4(0.f, 0.f, 0.f, 0.f);
    int e = beg + par;
    for (; e + 2 < end; e += 4) {
        int4 m0 = __ldg(&g_ep4[e]);
        int4 m1 = __ldg(&g_ep4[e + 2]);
        float fs0 = __int_as_float(l == 0 ? m0.y : (l == 1 ? m0.z : m0.w));
        float fs1 = __int_as_float(l == 0 ? m1.y : (l == 1 ? m1.z : m1.w));
        float4 v0 = __ldg((const float4*)g_h + m0.x * 16 + sub);
        float4 v1 = __ldg((const float4*)g_h + m1.x * 16 + sub);
        acc.x = fmaf(v0.x, fs0, fmaf(v1.x, fs1, acc.x));
        acc.y = fmaf(v0.y, fs0, fmaf(v1.y, fs1, acc.y));
        acc.z = fmaf(v0.z, fs0, fmaf(v1.z, fs1, acc.z));
        acc.w = fmaf(v0.w, fs0, fmaf(v1.w, fs1, acc.w));
    }
    if (e < end) {
        int4 m0 = __ldg(&g_ep4[e]);
        float fs0 = __int_as_float(l == 0 ? m0.y : (l == 1 ? m0.z : m0.w));
        float4 v0 = __ldg((const float4*)g_h + m0.x * 16 + sub);
        acc.x = fmaf(v0.x, fs0, acc.x);
        acc.y = fmaf(v0.y, fs0, acc.y);
        acc.z = fmaf(v0.z, fs0, acc.z);
        acc.w = fmaf(v0.w, fs0, acc.w);
    }
    acc.x += __shfl_xor_sync(0xffffffff, acc.x, 16);
    acc.y += __shfl_xor_sync(0xffffffff, acc.y, 16);
    acc.z += __shfl_xor_sync(0xffffffff, acc.z, 16);
    acc.w += __shfl_xor_sync(0xffffffff, acc.w, 16);
    if (par == 0) ((float4*)g_agg)[gw * 16 + sub] = acc;
}

// ============ node MLP: register weights, thread-per-column, 4 nodes/iter ======
__global__ void __launch_bounds__(128, 3) node_kernel(
    const float* __restrict__ iW1, const float* __restrict__ ib1,
    const float* __restrict__ iW2, const float* __restrict__ ib2,
    const float* __restrict__ gam, const float* __restrict__ bet,
    int do_mean) {
    __shared__ __align__(16) float sa[4][64];
    __shared__ __align__(16) float st[4][64];
    __shared__ float sm[128];
    int tid = threadIdx.x;
    int half = tid >> 6, j = tid & 63;
    float w1[64], w2[64];
    #pragma unroll
    for (int i = 0; i < 64; i++) {
        w1[i] = iW1[i * 64 + j];
        w2[i] = iW2[i * 64 + j];
    }
    float b1 = ib1[j], b2 = ib2[j];
    float gm = gam[j] * INVBN, bt = bet[j];
    float ms = 0.0f;

    for (int n0 = blockIdx.x * 4; n0 < Nn; n0 += gridDim.x * 4) {
        int nA = n0 + half, nB = n0 + 2 + half;      // Nn % 4 == 0 -> valid
        float aA = g_agg[nA * 64 + j];
        float aB = g_agg[nB * 64 + j];
        sa[half][j] = aA;
        sa[half + 2][j] = aB;
        __syncthreads();
        float acc0 = b1, acc1 = b1;
        const float4* A0 = (const float4*)sa[half];
        const float4* A1 = (const float4*)sa[half + 2];
        #pragma unroll
        for (int i4 = 0; i4 < 16; i4++) {
            float4 u = A0[i4];
            float4 v = A1[i4];
            acc0 = fmaf(u.x, w1[i4 * 4 + 0], acc0);
            acc1 = fmaf(v.x, w1[i4 * 4 + 0], acc1);
            acc0 = fmaf(u.y, w1[i4 * 4 + 1], acc0);
            acc1 = fmaf(v.y, w1[i4 * 4 + 1], acc1);
            acc0 = fmaf(u.z, w1[i4 * 4 + 2], acc0);
            acc1 = fmaf(v.z, w1[i4 * 4 + 2], acc1);
            acc0 = fmaf(u.w, w1[i4 * 4 + 3], acc0);
            acc1 = fmaf(v.w, w1[i4 * 4 + 3], acc1);
        }
        st[half][j] = sp(acc0);
        st[half + 2][j] = sp(acc1);
        __syncthreads();
        float o0 = b2, o1 = b2;
        const float4* T0 = (const float4*)st[half];
        const float4* T1 = (const float4*)st[half + 2];
        #pragma unroll
        for (int i4 = 0; i4 < 16; i4++) {
            float4 u = T0[i4];
            float4 v = T1[i4];
            o0 = fmaf(u.x, w2[i4 * 4 + 0], o0);
            o1 = fmaf(v.x, w2[i4 * 4 + 0], o1);
            o0 = fmaf(u.y, w2[i4 * 4 + 1], o0);
            o1 = fmaf(v.y, w2[i4 * 4 + 1], o1);
            o0 = fmaf(u.z, w2[i4 * 4 + 2], o0);
            o1 = fmaf(v.z, w2[i4 * 4 + 2], o1);
            o0 = fmaf(u.w, w2[i4 * 4 + 3], o0);
            o1 = fmaf(v.w, w2[i4 * 4 + 3], o1);
        }
        float h0 = g_h[nA * 64 + j] + fmaf(o0, gm, bt);
        float h1 = g_h[nB * 64 + j] + fmaf(o1, gm, bt);
        g_h[nA * 64 + j] = h0;
        g_h[nB * 64 + j] = h1;
        ms += h0 + h1;
    }
    if (do_mean) {
        sm[tid] = ms;
        __syncthreads();
        if (half == 0) atomicAdd(&g_mean[j], sm[j] + sm[j + 64]);
    }
}

// ---- final head ----
__global__ void final_kernel(const float* __restrict__ oW1, const float* __restrict__ ob1,
                             const float* __restrict__ og1, const float* __restrict__ obt1,
                             const float* __restrict__ oW2, const float* __restrict__ ob2,
                             const float* __restrict__ og2, const float* __restrict__ obt2,
                             const float* __restrict__ fiW, const float* __restrict__ fib,
                             float* __restrict__ out) {
    __shared__ float gv[64], s1[32], s2[32];
    int t = threadIdx.x;  // 64 threads
    gv[t] = g_mean[t] * (1.0f / (float)Nn);
    __syncthreads();
    if (t < 32) {
        float acc = ob1[t];
        #pragma unroll
        for (int i = 0; i < 64; i++) acc = fmaf(gv[i], oW1[i * 32 + t], acc);
        s1[t] = fmaf(sp(acc) * INVBN, og1[t], obt1[t]);
    }
    __syncthreads();
    if (t < 32) {
        float acc = ob2[t];
        #pragma unroll
        for (int i = 0; i < 32; i++) acc = fmaf(s1[i], oW2[i * 32 + t], acc);
        s2[t] = fmaf(sp(acc) * INVBN, og2[t], obt2[t]);
    }
    __syncthreads();
    if (t < 3) {
        float acc = fib[t];
        #pragma unroll
        for (int i = 0; i < 32; i++) acc = fmaf(s2[i], fiW[i * 3 + t], acc);
        out[t] = acc;
    }
}

extern "C" void kernel_launch(void* const* d_in, const int* in_sizes, int n_in,
                              void* d_out, int out_size) {
    const float* x    = (const float*)d_in[0];
    const int*   eidx = (const int*)  d_in[1];
    const float* dist = (const float*)d_in[2];
    const float* embW = (const float*)d_in[4];
    const float* embB = (const float*)d_in[5];
    const float* fW1  = (const float*)d_in[6];
    const float* fb1  = (const float*)d_in[7];
    const float* fW2  = (const float*)d_in[8];
    const float* fb2  = (const float*)d_in[9];
    const float* iW1  = (const float*)d_in[10];
    const float* ib1  = (const float*)d_in[11];
    const float* iW2  = (const float*)d_in[12];
    const float* ib2  = (const float*)d_in[13];
    const float* gam  = (const float*)d_in[14];
    const float* bet  = (const float*)d_in[15];
    const float* oW1  = (const float*)d_in[16];
    const float* ob1  = (const float*)d_in[17];
    const float* og1  = (const float*)d_in[18];
    const float* obt1 = (const float*)d_in[19];
    const float* oW2  = (const float*)d_in[20];
    const float* ob2  = (const float*)d_in[21];
    const float* og2  = (const float*)d_in[22];
    const float* obt2 = (const float*)d_in[23];
    const float* fiW  = (const float*)d_in[24];
    const float* fib  = (const float*)d_in[25];
    float* out = (float*)d_out;

    table_kernel<<<(Ll * Kt) / 256, 256>>>(fW1, fb1, fW2, fb2);
    embed_kernel<<<(Nn * 16 + 255) / 256, 256>>>(x, embW, embB);
    hist_kernel<<<(Ee + 255) / 256, 256>>>(eidx);
    scan_kernel<<<NB1, 512>>>();
    fill_kernel<<<(Ee + 255) / 256, 256>>>(eidx, dist);

    for (int l = 0; l < Ll; l++) {
        agg_kernel<<<(Nn * 32 + 255) / 256, 256>>>(l);
        node_kernel<<<444, 128>>>(iW1 + l * 4096, ib1 + l * 64,
                                  iW2 + l * 4096, ib2 + l * 64,
                                  gam + l * 64, bet + l * 64,
                                  (l == Ll - 1) ? 1 : 0);
    }

    final_kernel<<<1, 64>>>(oW1, ob1, og1, obt1, oW2, ob2, og2, obt2,
                            fiW, fib, out);
}

// round 8
// speedup vs baseline: 1.2670x; 1.0613x over previous
#include <cuda_runtime.h>
#include <math.h>

#define Nn 100000
#define Ee 1600000
#define Hh 64
#define Ll 3
#define Kt 8192
#define CUT 5.0f
#define INVBN 0.9995003747f   // 1/sqrt(1+1e-3)
#define NB1 98                // ceil(Nn/1024) scan blocks

typedef unsigned long long ull;

// ---- static device scratch ----
__device__ __align__(256) float g_h[Nn * Hh];       // node features, 25.6 MB
__device__ __align__(256) float g_agg[Nn * Hh];     // aggregation target, 25.6 MB
__device__ __align__(256) int4  g_ep4[Ee];          // (col, fs0, fs1, fs2), 25.6 MB
__device__ int   g_cnt[Nn];
__device__ int   g_off[Nn];
__device__ int   g_cur[Nn];
__device__ ull   g_state[NB1];                      // lookback scan states
__device__ float g_table[Ll * Kt];
__device__ float g_mean[Hh];

__device__ __forceinline__ float sp(float x) {      // softplus, stable
    return fmaxf(x, 0.0f) + log1pf(expf(-fabsf(x)));
}

// ---- table: fs(d)*cut(d); fW2 rowsums computed per-block in smem ----
__global__ void table_kernel(const float* __restrict__ fW1,
                             const float* __restrict__ fb1,
                             const float* __restrict__ fW2,
                             const float* __restrict__ fb2) {
    int t = blockIdx.x * 256 + threadIdx.x;       // grid 96x256 == Ll*Kt
    int l = t >> 13;                              // same l for whole block
    __shared__ float sw2[64];
    __shared__ float sb2;
    if (threadIdx.x < 64) {
        const float* p = fW2 + l * Hh * Hh + threadIdx.x * Hh;
        float s = 0.0f;
        #pragma unroll
        for (int k = 0; k < Hh; k++) s += p[k];
        sw2[threadIdx.x] = s;
    }
    if (threadIdx.x == 64) {
        float s = 0.0f;
        for (int k = 0; k < Hh; k++) s += fb2[l * Hh + k];
        sb2 = s;
    }
    __syncthreads();
    int k = t & (Kt - 1);
    float d = k * (CUT / (float)(Kt - 1));
    float s = d * (2.0f / CUT) - 1.0f;
    const float* w1 = fW1 + l * Hh;
    const float* b1 = fb1 + l * Hh;
    float acc = sb2;
    #pragma unroll 8
    for (int j = 0; j < Hh; j++)
        acc = fmaf(tanhf(fmaf(s, w1[j], b1[j])), sw2[j], acc);
    float cut = 0.5f * (cosf(d * (float)(M_PI / 5.0)) + 1.0f);
    g_table[t] = acc * cut;
}

// ---- embedding: h = x @ emb_W + emb_b ; also zero cnt/mean/scan-state ----
__global__ void embed_kernel(const float* __restrict__ x,
                             const float* __restrict__ W,
                             const float* __restrict__ b) {
    __shared__ float sW[16 * 64];
    __shared__ float sb[64];
    int tid = threadIdx.x;
    for (int i = tid; i < 16 * 64; i += 256) sW[i] = W[i];
    if (tid < 64) sb[tid] = b[tid];
    __syncthreads();
    int t = blockIdx.x * 256 + tid;
    // side duties (disjoint ranges, cheap)
    if (t < Nn) g_cnt[t] = 0;
    if (t < Hh) g_mean[t] = 0.0f;
    if (t < NB1) g_state[t] = 0ull;
    if (t >= Nn * 16) return;
    int n = t >> 4, q = t & 15, j0 = q * 4;
    const float* xr = x + n * 16;
    float4 acc = make_float4(sb[j0], sb[j0 + 1], sb[j0 + 2], sb[j0 + 3]);
    #pragma unroll
    for (int i = 0; i < 16; i++) {
        float xi = xr[i];
        acc.x = fmaf(xi, sW[i * 64 + j0 + 0], acc.x);
        acc.y = fmaf(xi, sW[i * 64 + j0 + 1], acc.y);
        acc.z = fmaf(xi, sW[i * 64 + j0 + 2], acc.z);
        acc.w = fmaf(xi, sW[i * 64 + j0 + 3], acc.w);
    }
    ((float4*)g_h)[t] = acc;
}

__global__ void hist_kernel(const int* __restrict__ eidx) {
    int e = blockIdx.x * blockDim.x + threadIdx.x;
    if (e < Ee) atomicAdd(&g_cnt[eidx[e]], 1);
}

// ---- single-pass decoupled-lookback exclusive scan of g_cnt -> g_off/g_cur ----
__global__ void __launch_bounds__(1024) scan_kernel() {
    int bid = blockIdx.x;
    int i = bid * 1024 + threadIdx.x;
    int v = (i < Nn) ? g_cnt[i] : 0;
    int lane = threadIdx.x & 31, w = threadIdx.x >> 5;
    int x = v;
    #pragma unroll
    for (int off = 1; off < 32; off <<= 1) {
        int y = __shfl_up_sync(0xffffffff, x, off);
        if (lane >= off) x += y;
    }
    __shared__ int wsum[32], wpre[32];
    __shared__ int stotal, sprefix;
    if (lane == 31) wsum[w] = x;
    __syncthreads();
    if (threadIdx.x < 32) {
        int s = wsum[threadIdx.x];
        int xs = s;
        #pragma unroll
        for (int off = 1; off < 32; off <<= 1) {
            int y = __shfl_up_sync(0xffffffff, xs, off);
            if ((int)threadIdx.x >= off) xs += y;
        }
        wpre[threadIdx.x] = xs - s;
        if (threadIdx.x == 31) stotal = xs;
    }
    __syncthreads();
    int total = stotal;
    if (threadIdx.x == 0) {
        if (bid == 0) {
            sprefix = 0;
            atomicExch(&g_state[0], (2ull << 32) | (unsigned)total);
        } else {
            atomicExch(&g_state[bid], (1ull << 32) | (unsigned)total);
            ull run = 0;
            int p = bid - 1;
            while (true) {
                ull sv = atomicAdd(&g_state[p], 0ull);
                unsigned st = (unsigned)(sv >> 32);
                if (st == 0u) { __nanosleep(32); continue; }
                run += (unsigned)sv;
                if (st == 2u) break;
                p--;
            }
            sprefix = (int)run;
            atomicExch(&g_state[bid], (2ull << 32) | (unsigned)(run + total));
        }
    }
    __syncthreads();
    if (i < Nn) {
        int o = x - v + wpre[w] + sprefix;
        g_off[i] = o;
        g_cur[i] = o;
    }
}

// scatter edges into CSR order; one int4 record (col, fs0, fs1, fs2)
__global__ void fill_kernel(const int* __restrict__ eidx,
                            const float* __restrict__ dist) {
    int e = blockIdx.x * blockDim.x + threadIdx.x;
    if (e >= Ee) return;
    int r = eidx[e];
    int c = eidx[Ee + e];
    float d = __ldg(dist + e);
    float u = d * ((float)(Kt - 1) / CUT);
    u = fminf(fmaxf(u, 0.0f), (float)(Kt - 2) + 0.999f);
    int i = (int)u;
    float fr = u - (float)i;
    float fs[Ll];
    #pragma unroll
    for (int l = 0; l < Ll; l++) {
        const float* tb = g_table + l * Kt;
        float t0 = __ldg(tb + i), t1 = __ldg(tb + i + 1);
        fs[l] = fmaf(fr, t1 - t0, t0);
    }
    int pos = atomicAdd(&g_cur[r], 1);
    g_ep4[pos] = make_int4(c, __float_as_int(fs[0]),
                           __float_as_int(fs[1]), __float_as_int(fs[2]));
}

// ============ per-layer edge aggregation: warp per row, whole-warp per edge ====
// Records loaded coalesced (1/lane), broadcast via shfl; every gather is an
// independent LDG.64 -> deep MLP; no end-of-row reduction needed.
__global__ void __launch_bounds__(256) agg_kernel(int l) {
    int gw = (blockIdx.x * 256 + threadIdx.x) >> 5;
    if (gw >= Nn) return;
    int lane = threadIdx.x & 31;
    int beg = g_off[gw], deg = g_cnt[gw];
    float2 acc = make_float2(0.0f, 0.0f);
    const float2* hb = (const float2*)g_h;
    for (int base = 0; base < deg; base += 32) {
        int rem = deg - base;
        if (rem > 32) rem = 32;
        int col_r = 0, fs_r = 0;
        if (lane < rem) {
            int4 m = __ldg(&g_ep4[beg + base + lane]);
            col_r = m.x;
            fs_r = (l == 0) ? m.y : (l == 1 ? m.z : m.w);
        }
        int d = 0;
        #pragma unroll 4
        for (; d + 4 <= rem; d += 4) {
            int c0 = __shfl_sync(0xffffffff, col_r, d + 0);
            int c1 = __shfl_sync(0xffffffff, col_r, d + 1);
            int c2 = __shfl_sync(0xffffffff, col_r, d + 2);
            int c3 = __shfl_sync(0xffffffff, col_r, d + 3);
            float f0 = __int_as_float(__shfl_sync(0xffffffff, fs_r, d + 0));
            float f1 = __int_as_float(__shfl_sync(0xffffffff, fs_r, d + 1));
            float f2 = __int_as_float(__shfl_sync(0xffffffff, fs_r, d + 2));
            float f3 = __int_as_float(__shfl_sync(0xffffffff, fs_r, d + 3));
            float2 v0 = __ldg(hb + c0 * 32 + lane);
            float2 v1 = __ldg(hb + c1 * 32 + lane);
            float2 v2 = __ldg(hb + c2 * 32 + lane);
            float2 v3 = __ldg(hb + c3 * 32 + lane);
            acc.x = fmaf(v0.x, f0, acc.x);
            acc.y = fmaf(v0.y, f0, acc.y);
            acc.x = fmaf(v1.x, f1, acc.x);
            acc.y = fmaf(v1.y, f1, acc.y);
            acc.x = fmaf(v2.x, f2, acc.x);
            acc.y = fmaf(v2.y, f2, acc.y);
            acc.x = fmaf(v3.x, f3, acc.x);
            acc.y = fmaf(v3.y, f3, acc.y);
        }
        for (; d < rem; d++) {
            int c0 = __shfl_sync(0xffffffff, col_r, d);
            float f0 = __int_as_float(__shfl_sync(0xffffffff, fs_r, d));
            float2 v0 = __ldg(hb + c0 * 32 + lane);
            acc.x = fmaf(v0.x, f0, acc.x);
            acc.y = fmaf(v0.y, f0, acc.y);
        }
    }
    ((float2*)g_agg)[gw * 32 + lane] = acc;
}

// ============ node MLP: register weights, thread-per-column, 4 nodes/iter ======
__global__ void __launch_bounds__(128, 3) node_kernel(
    const float* __restrict__ iW1, const float* __restrict__ ib1,
    const float* __restrict__ iW2, const float* __restrict__ ib2,
    const float* __restrict__ gam, const float* __restrict__ bet,
    int do_mean) {
    __shared__ __align__(16) float sa[4][64];
    __shared__ __align__(16) float st[4][64];
    __shared__ float sm[128];
    int tid = threadIdx.x;
    int half = tid >> 6, j = tid & 63;
    float w1[64], w2[64];
    #pragma unroll
    for (int i = 0; i < 64; i++) {
        w1[i] = iW1[i * 64 + j];
        w2[i] = iW2[i * 64 + j];
    }
    float b1 = ib1[j], b2 = ib2[j];
    float gm = gam[j] * INVBN, bt = bet[j];
    float ms = 0.0f;

    for (int n0 = blockIdx.x * 4; n0 < Nn; n0 += gridDim.x * 4) {
        int nA = n0 + half, nB = n0 + 2 + half;      // Nn % 4 == 0 -> valid
        float aA = g_agg[nA * 64 + j];
        float aB = g_agg[nB * 64 + j];
        sa[half][j] = aA;
        sa[half + 2][j] = aB;
        __syncthreads();
        float acc0 = b1, acc1 = b1;
        const float4* A0 = (const float4*)sa[half];
        const float4* A1 = (const float4*)sa[half + 2];
        #pragma unroll
        for (int i4 = 0; i4 < 16; i4++) {
            float4 u = A0[i4];
            float4 v = A1[i4];
            acc0 = fmaf(u.x, w1[i4 * 4 + 0], acc0);
            acc1 = fmaf(v.x, w1[i4 * 4 + 0], acc1);
            acc0 = fmaf(u.y, w1[i4 * 4 + 1], acc0);
            acc1 = fmaf(v.y, w1[i4 * 4 + 1], acc1);
            acc0 = fmaf(u.z, w1[i4 * 4 + 2], acc0);
            acc1 = fmaf(v.z, w1[i4 * 4 + 2], acc1);
            acc0 = fmaf(u.w, w1[i4 * 4 + 3], acc0);
            acc1 = fmaf(v.w, w1[i4 * 4 + 3], acc1);
        }
        st[half][j] = sp(acc0);
        st[half + 2][j] = sp(acc1);
        __syncthreads();
        float o0 = b2, o1 = b2;
        const float4* T0 = (const float4*)st[half];
        const float4* T1 = (const float4*)st[half + 2];
        #pragma unroll
        for (int i4 = 0; i4 < 16; i4++) {
            float4 u = T0[i4];
            float4 v = T1[i4];
            o0 = fmaf(u.x, w2[i4 * 4 + 0], o0);
            o1 = fmaf(v.x, w2[i4 * 4 + 0], o1);
            o0 = fmaf(u.y, w2[i4 * 4 + 1], o0);
            o1 = fmaf(v.y, w2[i4 * 4 + 1], o1);
            o0 = fmaf(u.z, w2[i4 * 4 + 2], o0);
            o1 = fmaf(v.z, w2[i4 * 4 + 2], o1);
            o0 = fmaf(u.w, w2[i4 * 4 + 3], o0);
            o1 = fmaf(v.w, w2[i4 * 4 + 3], o1);
        }
        float h0 = g_h[nA * 64 + j] + fmaf(o0, gm, bt);
        float h1 = g_h[nB * 64 + j] + fmaf(o1, gm, bt);
        g_h[nA * 64 + j] = h0;
        g_h[nB * 64 + j] = h1;
        ms += h0 + h1;
    }
    if (do_mean) {
        sm[tid] = ms;
        __syncthreads();
        if (half == 0) atomicAdd(&g_mean[j], sm[j] + sm[j + 64]);
    }
}

// ---- final head ----
__global__ void final_kernel(const float* __restrict__ oW1, const float* __restrict__ ob1,
                             const float* __restrict__ og1, const float* __restrict__ obt1,
                             const float* __restrict__ oW2, const float* __restrict__ ob2,
                             const float* __restrict__ og2, const float* __restrict__ obt2,
                             const float* __restrict__ fiW, const float* __restrict__ fib,
                             float* __restrict__ out) {
    __shared__ float gv[64], s1[32], s2[32];
    int t = threadIdx.x;  // 64 threads
    gv[t] = g_mean[t] * (1.0f / (float)Nn);
    __syncthreads();
    if (t < 32) {
        float acc = ob1[t];
        #pragma unroll
        for (int i = 0; i < 64; i++) acc = fmaf(gv[i], oW1[i * 32 + t], acc);
        s1[t] = fmaf(sp(acc) * INVBN, og1[t], obt1[t]);
    }
    __syncthreads();
    if (t < 32) {
        float acc = ob2[t];
        #pragma unroll
        for (int i = 0; i < 32; i++) acc = fmaf(s1[i], oW2[i * 32 + t], acc);
        s2[t] = fmaf(sp(acc) * INVBN, og2[t], obt2[t]);
    }
    __syncthreads();
    if (t < 3) {
        float acc = fib[t];
        #pragma unroll
        for (int i = 0; i < 32; i++) acc = fmaf(s2[i], fiW[i * 3 + t], acc);
        out[t] = acc;
    }
}

extern "C" void kernel_launch(void* const* d_in, const int* in_sizes, int n_in,
                              void* d_out, int out_size) {
    const float* x    = (const float*)d_in[0];
    const int*   eidx = (const int*)  d_in[1];
    const float* dist = (const float*)d_in[2];
    const float* embW = (const float*)d_in[4];
    const float* embB = (const float*)d_in[5];
    const float* fW1  = (const float*)d_in[6];
    const float* fb1  = (const float*)d_in[7];
    const float* fW2  = (const float*)d_in[8];
    const float* fb2  = (const float*)d_in[9];
    const float* iW1  = (const float*)d_in[10];
    const float* ib1  = (const float*)d_in[11];
    const float* iW2  = (const float*)d_in[12];
    const float* ib2  = (const float*)d_in[13];
    const float* gam  = (const float*)d_in[14];
    const float* bet  = (const float*)d_in[15];
    const float* oW1  = (const float*)d_in[16];
    const float* ob1  = (const float*)d_in[17];
    const float* og1  = (const float*)d_in[18];
    const float* obt1 = (const float*)d_in[19];
    const float* oW2  = (const float*)d_in[20];
    const float* ob2  = (const float*)d_in[21];
    const float* og2  = (const float*)d_in[22];
    const float* obt2 = (const float*)d_in[23];
    const float* fiW  = (const float*)d_in[24];
    const float* fib  = (const float*)d_in[25];
    float* out = (float*)d_out;

    table_kernel<<<(Ll * Kt) / 256, 256>>>(fW1, fb1, fW2, fb2);
    embed_kernel<<<(Nn * 16 + 255) / 256, 256>>>(x, embW, embB);
    hist_kernel<<<(Ee + 255) / 256, 256>>>(eidx);
    scan_kernel<<<NB1, 1024>>>();
    fill_kernel<<<(Ee + 255) / 256, 256>>>(eidx, dist);

    for (int l = 0; l < Ll; l++) {
        agg_kernel<<<(Nn * 32 + 255) / 256, 256>>>(l);
        node_kernel<<<444, 128>>>(iW1 + l * 4096, ib1 + l * 64,
                                  iW2 + l * 4096, ib2 + l * 64,
                                  gam + l * 64, bet + l * 64,
                                  (l == Ll - 1) ? 1 : 0);
    }

    final_kernel<<<1, 64>>>(oW1, ob1, og1, obt1, oW2, ob2, og2, obt2,
                            fiW, fib, out);
}